// round 7
// baseline (speedup 1.0000x reference)
#include <cuda_runtime.h>
#include <cuda_bf16.h>
#include <cstdint>

#define N_NODES 50000
#define N_EDGES 600000
#define D 128
#define D2 256
#define NLAYERS 5

// ---------------- scratch (static device memory; no allocations) -------------
__device__ float g_h[N_NODES * D];
__device__ float g_z[N_NODES * D];
__device__ float g_y1[N_NODES * D2];
__device__ __nv_bfloat16 g_zh[N_NODES * D],  g_zl[N_NODES * D];
__device__ __nv_bfloat16 g_y1h[N_NODES * D2], g_y1l[N_NODES * D2];
__device__ __nv_bfloat16 g_w1h[NLAYERS * D * D2], g_w1l[NLAYERS * D * D2];
__device__ __nv_bfloat16 g_w2h[NLAYERS * D2 * D], g_w2l[NLAYERS * D2 * D];
__device__ float g_stats1[2 * D2];
__device__ float g_stats2[2 * D];
__device__ float g_scale1[D2], g_shift1[D2];
__device__ float g_scale2[D], g_shift2[D];

// ---------------- helpers ----------------------------------------------------
__device__ __forceinline__ uint32_t smem_u32(const void* p) {
    return (uint32_t)__cvta_generic_to_shared(p);
}
__device__ __forceinline__ void ldsm4(uint32_t addr, uint32_t& r0, uint32_t& r1,
                                      uint32_t& r2, uint32_t& r3) {
    asm volatile("ldmatrix.sync.aligned.m8n8.x4.shared.b16 {%0,%1,%2,%3}, [%4];"
                 : "=r"(r0), "=r"(r1), "=r"(r2), "=r"(r3) : "r"(addr));
}
__device__ __forceinline__ void ldsm4t(uint32_t addr, uint32_t& r0, uint32_t& r1,
                                       uint32_t& r2, uint32_t& r3) {
    asm volatile("ldmatrix.sync.aligned.m8n8.x4.trans.shared.b16 {%0,%1,%2,%3}, [%4];"
                 : "=r"(r0), "=r"(r1), "=r"(r2), "=r"(r3) : "r"(addr));
}
__device__ __forceinline__ void mma16816(float* c, const uint32_t* a, const uint32_t* b) {
    asm volatile(
        "mma.sync.aligned.m16n8k16.row.col.f32.bf16.bf16.f32 "
        "{%0,%1,%2,%3}, {%4,%5,%6,%7}, {%8,%9}, {%0,%1,%2,%3};"
        : "+f"(c[0]), "+f"(c[1]), "+f"(c[2]), "+f"(c[3])
        : "r"(a[0]), "r"(a[1]), "r"(a[2]), "r"(a[3]), "r"(b[0]), "r"(b[1]));
}
__device__ __forceinline__ void cp_async16(uint32_t dst, const void* src, int szbytes) {
    asm volatile("cp.async.cg.shared.global [%0], [%1], 16, %2;"
                 :: "r"(dst), "l"(src), "r"(szbytes));
}
__device__ __forceinline__ void cp_commit() { asm volatile("cp.async.commit_group;"); }
__device__ __forceinline__ void cp_wait1() { asm volatile("cp.async.wait_group 1;"); }
__device__ __forceinline__ void split2(float x0, float x1,
                                       __nv_bfloat162& hi, __nv_bfloat162& lo) {
    __nv_bfloat16 h0 = __float2bfloat16_rn(x0);
    __nv_bfloat16 h1 = __float2bfloat16_rn(x1);
    hi = __nv_bfloat162(h0, h1);
    lo = __nv_bfloat162(__float2bfloat16_rn(x0 - __bfloat162float(h0)),
                        __float2bfloat16_rn(x1 - __bfloat162float(h1)));
}

// ---------------- node embedding + z seed + stats zero -----------------------
__global__ void embed_kernel(const int* __restrict__ x,
                             const float* __restrict__ atom_emb,
                             const float* __restrict__ eps_p) {
    int idx = blockIdx.x * blockDim.x + threadIdx.x;
    if (idx < 2 * D2) g_stats1[idx] = 0.f;
    if (idx < 2 * D)  g_stats2[idx] = 0.f;
    int node = idx >> 5, lane = idx & 31;
    if (node >= N_NODES) return;
    const int* xr = x + node * 9;
    float4 acc = make_float4(0.f, 0.f, 0.f, 0.f);
#pragma unroll
    for (int f = 0; f < 9; f++) {
        int v = __ldg(xr + f);
        float4 t = ((const float4*)(atom_emb + (size_t)(f * 64 + v) * D))[lane];
        acc.x += t.x; acc.y += t.y; acc.z += t.z; acc.w += t.w;
    }
    ((float4*)(g_h + (size_t)node * D))[lane] = acc;
    float s = 1.f + __ldg(eps_p);
    acc.x *= s; acc.y *= s; acc.z *= s; acc.w *= s;
    ((float4*)(g_z + (size_t)node * D))[lane] = acc;
}

// ---------------- edge scatter: z[dst] += relu(h[src]+ea)*ew -----------------
__global__ void edge_kernel(const int* __restrict__ edge_index,
                            const int* __restrict__ edge_attr,
                            const float* __restrict__ edge_weight,
                            const float* __restrict__ bond_emb, int l) {
    __shared__ __align__(16) float sb[3 * 8 * D];
    const float* be = bond_emb + (size_t)l * 3 * 8 * D;
    for (int i = threadIdx.x; i < 3 * 8 * D; i += blockDim.x) sb[i] = be[i];
    __syncthreads();

    const int* src = edge_index;
    const int* dst = edge_index + N_EDGES;
    int gw = (blockIdx.x * blockDim.x + threadIdx.x) >> 5;
    int lane = threadIdx.x & 31;
    int nw = (gridDim.x * blockDim.x) >> 5;

    for (int e = gw; e < N_EDGES; e += nw) {
        int s = __ldg(src + e);
        int d = __ldg(dst + e);
        float w = __ldg(edge_weight + e);
        int a0 = __ldg(edge_attr + e * 3 + 0);
        int a1 = __ldg(edge_attr + e * 3 + 1);
        int a2 = __ldg(edge_attr + e * 3 + 2);
        float4 hv = ((const float4*)(g_h + (size_t)s * D))[lane];
        float4 e0 = ((const float4*)(sb + a0 * D))[lane];
        float4 e1 = ((const float4*)(sb + (8 + a1) * D))[lane];
        float4 e2 = ((const float4*)(sb + (16 + a2) * D))[lane];
        float4 m;
        m.x = fmaxf(hv.x + e0.x + e1.x + e2.x, 0.f) * w;
        m.y = fmaxf(hv.y + e0.y + e1.y + e2.y, 0.f) * w;
        m.z = fmaxf(hv.z + e0.z + e1.z + e2.z, 0.f) * w;
        m.w = fmaxf(hv.w + e0.w + e1.w + e2.w, 0.f) * w;
        atomicAdd(((float4*)(g_z + (size_t)d * D)) + lane, m);
    }
}

// ---------------- fp32 -> bf16 hi/lo split (plain) ---------------------------
__global__ void split_kernel(const float* __restrict__ src,
                             __nv_bfloat16* __restrict__ dh,
                             __nv_bfloat16* __restrict__ dl, int n4) {
    int i = blockIdx.x * blockDim.x + threadIdx.x;
    if (i >= n4) return;
    float4 v = ((const float4*)src)[i];
    __nv_bfloat162 h0, l0, h1, l1;
    split2(v.x, v.y, h0, l0);
    split2(v.z, v.w, h1, l1);
    ((__nv_bfloat162*)dh)[i * 2]     = h0;
    ((__nv_bfloat162*)dh)[i * 2 + 1] = h1;
    ((__nv_bfloat162*)dl)[i * 2]     = l0;
    ((__nv_bfloat162*)dl)[i * 2 + 1] = l1;
}

// ---------------- y1 -> relu(bn1(y1)) -> bf16 hi/lo --------------------------
__global__ void split_bn_kernel(const float* __restrict__ src,
                                __nv_bfloat16* __restrict__ dh,
                                __nv_bfloat16* __restrict__ dl) {
    int i = blockIdx.x * blockDim.x + threadIdx.x;
    if (i >= N_NODES * (D2 / 4)) return;
    int c4 = i & (D2 / 4 - 1);
    float4 v = ((const float4*)src)[i];
    float4 sc = ((const float4*)g_scale1)[c4];
    float4 sh = ((const float4*)g_shift1)[c4];
    v.x = fmaxf(fmaf(v.x, sc.x, sh.x), 0.f);
    v.y = fmaxf(fmaf(v.y, sc.y, sh.y), 0.f);
    v.z = fmaxf(fmaf(v.z, sc.z, sh.z), 0.f);
    v.w = fmaxf(fmaf(v.w, sc.w, sh.w), 0.f);
    __nv_bfloat162 h0, l0, h1, l1;
    split2(v.x, v.y, h0, l0);
    split2(v.z, v.w, h1, l1);
    ((__nv_bfloat162*)dh)[i * 2]     = h0;
    ((__nv_bfloat162*)dh)[i * 2 + 1] = h1;
    ((__nv_bfloat162*)dl)[i * 2]     = l0;
    ((__nv_bfloat162*)dl)[i * 2 + 1] = l1;
}

// ================ bf16 hi/lo tensor-core GEMM, 3-stage cp.async ==============
// C[M x NOUT] = (Ah+Al) @ (Bh+Bl) + bias  (dropping Al*Bl), + column stats.
// 64x128x32 block tile, 256 threads (8 warps: 2M x 4N, 32x32 per warp).
#define A_STRIDE 40    // bf16 per A smem row (80B, conflict-free)
#define B_STRIDE 136   // bf16 per B smem row (272B, conflict-free)
#define GBM 64
#define GBN 128
#define GBK 32
#define A_BYTES (GBM * A_STRIDE * 2)                  // 5120
#define B_BYTES (GBK * B_STRIDE * 2)                  // 8704
#define STAGE_BYTES (2 * A_BYTES + 2 * B_BYTES)       // 27648
#define N_STAGES 3
#define SMEM_GEMM (N_STAGES * STAGE_BYTES)            // 82944

template <int K, int NOUT>
__global__ __launch_bounds__(256)
void gemm_bf16_kernel(const __nv_bfloat16* __restrict__ Ah_g,
                      const __nv_bfloat16* __restrict__ Al_g,
                      const __nv_bfloat16* __restrict__ Bh_g,
                      const __nv_bfloat16* __restrict__ Bl_g,
                      const float* __restrict__ bias, float* __restrict__ C,
                      float* __restrict__ stats) {
    const int NT = K / GBK;
    extern __shared__ __align__(16) char smem[];
    __shared__ float ssum[GBN], ssq[GBN];

    int tid = threadIdx.x;
    int lane = tid & 31, warp = tid >> 5;
    int wm = warp & 1, wn = warp >> 1;          // 2 warps M x 4 warps N
    int rowBase = blockIdx.y * GBM;
    int colBase = blockIdx.x * GBN;

    if (tid < GBN) { ssum[tid] = 0.f; ssq[tid] = 0.f; }

    float acc[2][4][4];
#pragma unroll
    for (int i = 0; i < 2; i++)
#pragma unroll
        for (int j = 0; j < 4; j++)
#pragma unroll
            for (int q = 0; q < 4; q++) acc[i][j][q] = 0.f;

    auto pA_h = [&](int s) { return (__nv_bfloat16*)(smem + s * STAGE_BYTES); };
    auto pA_l = [&](int s) { return (__nv_bfloat16*)(smem + s * STAGE_BYTES + A_BYTES); };
    auto pB_h = [&](int s) { return (__nv_bfloat16*)(smem + s * STAGE_BYTES + 2 * A_BYTES); };
    auto pB_l = [&](int s) { return (__nv_bfloat16*)(smem + s * STAGE_BYTES + 2 * A_BYTES + B_BYTES); };

    // per-thread load coords
    int ar = tid >> 2, ac = (tid & 3) * 8;         // A: 64 rows x 4 chunks
    int agrow = rowBase + ar;
    int asz = (agrow < N_NODES) ? 16 : 0;

    auto LOADS = [&](int kt, int s) {
        cp_async16(smem_u32(pA_h(s) + ar * A_STRIDE + ac),
                   Ah_g + (size_t)agrow * K + kt + ac, asz);
        cp_async16(smem_u32(pA_l(s) + ar * A_STRIDE + ac),
                   Al_g + (size_t)agrow * K + kt + ac, asz);
#pragma unroll
        for (int i = 0; i < 2; i++) {
            int id = tid + i * 256;
            int r = id >> 4, c = (id & 15) * 8;
            cp_async16(smem_u32(pB_h(s) + r * B_STRIDE + c),
                       Bh_g + (size_t)(kt + r) * NOUT + colBase + c, 16);
            cp_async16(smem_u32(pB_l(s) + r * B_STRIDE + c),
                       Bl_g + (size_t)(kt + r) * NOUT + colBase + c, 16);
        }
    };

    int lr = lane & 15;
    int lc = (lane >> 4) << 3;

    LOADS(0, 0); cp_commit();
    if (NT > 1) { LOADS(GBK, 1); }
    cp_commit();

#pragma unroll 1
    for (int t = 0; t < NT; t++) {
        int s = t % N_STAGES;
        cp_wait1();                 // tile t arrived (≤1 group pending)
        __syncthreads();            // all warps done with tile t-1 (its stage is free)
        if (t + 2 < NT) LOADS((t + 2) * GBK, (t + 2) % N_STAGES);
        cp_commit();                // unconditional: keeps group accounting uniform

        const __nv_bfloat16* Ahs = pA_h(s);
        const __nv_bfloat16* Als = pA_l(s);
        const __nv_bfloat16* Bhs = pB_h(s);
        const __nv_bfloat16* Bls = pB_l(s);
#pragma unroll
        for (int ks = 0; ks < GBK; ks += 16) {
            uint32_t bh[4][2], bl[4][2];
#pragma unroll
            for (int nb = 0; nb < 2; nb++) {
                int ncol = wn * 32 + nb * 16 + lc;
                uint32_t r0, r1, r2, r3;
                ldsm4t(smem_u32(Bhs + (ks + lr) * B_STRIDE + ncol), r0, r1, r2, r3);
                bh[nb * 2][0] = r0; bh[nb * 2][1] = r1;
                bh[nb * 2 + 1][0] = r2; bh[nb * 2 + 1][1] = r3;
                ldsm4t(smem_u32(Bls + (ks + lr) * B_STRIDE + ncol), r0, r1, r2, r3);
                bl[nb * 2][0] = r0; bl[nb * 2][1] = r1;
                bl[nb * 2 + 1][0] = r2; bl[nb * 2 + 1][1] = r3;
            }
#pragma unroll
            for (int mf = 0; mf < 2; mf++) {
                int mrow = wm * 32 + mf * 16 + lr;
                uint32_t ah[4], al[4];
                ldsm4(smem_u32(Ahs + mrow * A_STRIDE + ks + lc), ah[0], ah[1], ah[2], ah[3]);
                ldsm4(smem_u32(Als + mrow * A_STRIDE + ks + lc), al[0], al[1], al[2], al[3]);
#pragma unroll
                for (int nf = 0; nf < 4; nf++) {
                    mma16816(acc[mf][nf], ah, bh[nf]);
                    mma16816(acc[mf][nf], ah, bl[nf]);
                    mma16816(acc[mf][nf], al, bh[nf]);
                }
            }
        }
    }

    // ---- epilogue: bias, store, per-column stats ----
    int crow = lane >> 2;
    int ccol = (lane & 3) * 2;
    float bcol8[4][2];
#pragma unroll
    for (int nf = 0; nf < 4; nf++) {
        bcol8[nf][0] = bias[colBase + wn * 32 + nf * 8 + ccol];
        bcol8[nf][1] = bias[colBase + wn * 32 + nf * 8 + ccol + 1];
    }
    float psum[4][2] = {}, psq[4][2] = {};
#pragma unroll
    for (int mf = 0; mf < 2; mf++)
#pragma unroll
        for (int r2 = 0; r2 < 2; r2++) {
            int r = rowBase + wm * 32 + mf * 16 + crow + r2 * 8;
            if (r < N_NODES) {
#pragma unroll
                for (int nf = 0; nf < 4; nf++) {
                    float v0 = acc[mf][nf][r2 * 2 + 0] + bcol8[nf][0];
                    float v1 = acc[mf][nf][r2 * 2 + 1] + bcol8[nf][1];
                    *(float2*)(C + (size_t)r * NOUT + colBase + wn * 32 + nf * 8 + ccol) =
                        make_float2(v0, v1);
                    psum[nf][0] += v0; psq[nf][0] += v0 * v0;
                    psum[nf][1] += v1; psq[nf][1] += v1 * v1;
                }
            }
        }
    __syncthreads();
#pragma unroll
    for (int nf = 0; nf < 4; nf++) {
        int c = wn * 32 + nf * 8 + ccol;
        atomicAdd(&ssum[c],     psum[nf][0]);
        atomicAdd(&ssum[c + 1], psum[nf][1]);
        atomicAdd(&ssq[c],      psq[nf][0]);
        atomicAdd(&ssq[c + 1],  psq[nf][1]);
    }
    __syncthreads();
    if (tid < GBN) {
        atomicAdd(&stats[colBase + tid], ssum[tid]);
        atomicAdd(&stats[NOUT + colBase + tid], ssq[tid]);
    }
}

// ---------------- BN stats -> scale/shift (and re-zero stats) ----------------
__global__ void finalize_kernel(float* __restrict__ stats,
                                const float* __restrict__ g, const float* __restrict__ b,
                                float* __restrict__ scale, float* __restrict__ shift, int C) {
    int c = threadIdx.x;
    if (c < C) {
        const float invn = 1.f / (float)N_NODES;
        float m = stats[c] * invn;
        float var = stats[C + c] * invn - m * m;
        float sc = g[c] * rsqrtf(var + 1e-5f);
        scale[c] = sc;
        shift[c] = b[c] - m * sc;
        stats[c] = 0.f;
        stats[C + c] = 0.f;
    }
}

// ---------------- apply BN2; write h + next-layer z seed (or final out) ------
__global__ void bn_apply_kernel(float* __restrict__ final_out,
                                const float* __restrict__ eps_p, int l) {
    int idx = blockIdx.x * blockDim.x + threadIdx.x;
    if (idx >= N_NODES * (D / 4)) return;
    int c4 = idx & 31;
    float4 v = ((const float4*)g_z)[idx];
    float4 sc = ((const float4*)g_scale2)[c4];
    float4 sh = ((const float4*)g_shift2)[c4];
    v.x = fmaf(v.x, sc.x, sh.x);
    v.y = fmaf(v.y, sc.y, sh.y);
    v.z = fmaf(v.z, sc.z, sh.z);
    v.w = fmaf(v.w, sc.w, sh.w);
    if (l < NLAYERS - 1) {
        v.x = fmaxf(v.x, 0.f); v.y = fmaxf(v.y, 0.f);
        v.z = fmaxf(v.z, 0.f); v.w = fmaxf(v.w, 0.f);
        ((float4*)g_h)[idx] = v;
        float s = 1.f + __ldg(eps_p + l + 1);
        v.x *= s; v.y *= s; v.z *= s; v.w *= s;
        ((float4*)g_z)[idx] = v;
    } else {
        ((float4*)final_out)[idx] = v;
    }
}

// ---------------- launcher ---------------------------------------------------
extern "C" void kernel_launch(void* const* d_in, const int* in_sizes, int n_in,
                              void* d_out, int out_size) {
    const int*   x           = (const int*)d_in[0];
    const int*   edge_index  = (const int*)d_in[1];
    const int*   edge_attr   = (const int*)d_in[2];
    const float* edge_weight = (const float*)d_in[3];
    const float* atom_emb    = (const float*)d_in[4];
    const float* bond_emb    = (const float*)d_in[5];
    const float* W1          = (const float*)d_in[6];
    const float* b1          = (const float*)d_in[7];
    const float* bn1_g       = (const float*)d_in[8];
    const float* bn1_b       = (const float*)d_in[9];
    const float* W2          = (const float*)d_in[10];
    const float* b2          = (const float*)d_in[11];
    const float* eps_p       = (const float*)d_in[12];
    const float* bn_g        = (const float*)d_in[13];
    const float* bn_b        = (const float*)d_in[14];
    float* out = (float*)d_out;

    float *p_z, *p_y1, *p_sc1, *p_sh1, *p_st1, *p_st2, *p_sc2, *p_sh2;
    __nv_bfloat16 *p_zh, *p_zl, *p_y1h, *p_y1l, *p_w1h, *p_w1l, *p_w2h, *p_w2l;
    cudaGetSymbolAddress((void**)&p_z,   g_z);
    cudaGetSymbolAddress((void**)&p_y1,  g_y1);
    cudaGetSymbolAddress((void**)&p_sc1, g_scale1);
    cudaGetSymbolAddress((void**)&p_sh1, g_shift1);
    cudaGetSymbolAddress((void**)&p_st1, g_stats1);
    cudaGetSymbolAddress((void**)&p_st2, g_stats2);
    cudaGetSymbolAddress((void**)&p_sc2, g_scale2);
    cudaGetSymbolAddress((void**)&p_sh2, g_shift2);
    cudaGetSymbolAddress((void**)&p_zh,  g_zh);
    cudaGetSymbolAddress((void**)&p_zl,  g_zl);
    cudaGetSymbolAddress((void**)&p_y1h, g_y1h);
    cudaGetSymbolAddress((void**)&p_y1l, g_y1l);
    cudaGetSymbolAddress((void**)&p_w1h, g_w1h);
    cudaGetSymbolAddress((void**)&p_w1l, g_w1l);
    cudaGetSymbolAddress((void**)&p_w2h, g_w2h);
    cudaGetSymbolAddress((void**)&p_w2l, g_w2l);

    cudaFuncSetAttribute(gemm_bf16_kernel<D, D2>,
                         cudaFuncAttributeMaxDynamicSharedMemorySize, SMEM_GEMM);
    cudaFuncSetAttribute(gemm_bf16_kernel<D2, D>,
                         cudaFuncAttributeMaxDynamicSharedMemorySize, SMEM_GEMM);

    const int ELT_BLOCKS = (N_NODES * (D / 4) + 255) / 256;
    const int MB = (N_NODES + GBM - 1) / GBM;
    const int WN4 = NLAYERS * D * D2 / 4;

    embed_kernel<<<(N_NODES * 32 + 255) / 256, 256>>>(x, atom_emb, eps_p);
    split_kernel<<<(WN4 + 255) / 256, 256>>>(W1, p_w1h, p_w1l, WN4);
    split_kernel<<<(WN4 + 255) / 256, 256>>>(W2, p_w2h, p_w2l, WN4);

    for (int l = 0; l < NLAYERS; l++) {
        edge_kernel<<<1184, 256>>>(edge_index, edge_attr, edge_weight, bond_emb, l);

        split_kernel<<<(N_NODES * (D / 4) + 255) / 256, 256>>>(p_z, p_zh, p_zl,
                                                               N_NODES * (D / 4));
        gemm_bf16_kernel<D, D2><<<dim3(D2 / GBN, MB), 256, SMEM_GEMM>>>(
            p_zh, p_zl, p_w1h + (size_t)l * D * D2, p_w1l + (size_t)l * D * D2,
            b1 + (size_t)l * D2, p_y1, p_st1);
        finalize_kernel<<<1, 256>>>(p_st1, bn1_g + (size_t)l * D2, bn1_b + (size_t)l * D2,
                                    p_sc1, p_sh1, D2);

        split_bn_kernel<<<(N_NODES * (D2 / 4) + 255) / 256, 256>>>(p_y1, p_y1h, p_y1l);
        gemm_bf16_kernel<D2, D><<<dim3(D / GBN, MB), 256, SMEM_GEMM>>>(
            p_y1h, p_y1l, p_w2h + (size_t)l * D2 * D, p_w2l + (size_t)l * D2 * D,
            b2 + (size_t)l * D, p_z, p_st2);
        finalize_kernel<<<1, 128>>>(p_st2, bn_g + (size_t)l * D, bn_b + (size_t)l * D,
                                    p_sc2, p_sh2, D);

        bn_apply_kernel<<<ELT_BLOCKS, 256>>>(out, eps_p, l);
    }
    (void)in_sizes; (void)n_in; (void)out_size;
}

// round 8
// speedup vs baseline: 1.2124x; 1.2124x over previous
#include <cuda_runtime.h>
#include <cuda_bf16.h>
#include <cstdint>

#define N_NODES 50000
#define N_EDGES 600000
#define D 128
#define D2 256
#define NLAYERS 5

// ---------------- scratch (static device memory; no allocations) -------------
__device__ float g_h[N_NODES * D];
__device__ float g_z[N_NODES * D];
__device__ float g_y1[N_NODES * D2];
__device__ __nv_bfloat16 g_w1h[NLAYERS * D * D2], g_w1l[NLAYERS * D * D2];
__device__ __nv_bfloat16 g_w2h[NLAYERS * D2 * D], g_w2l[NLAYERS * D2 * D];
__device__ float g_stats1[2 * D2];
__device__ float g_stats2[2 * D];
__device__ float g_scale1[D2], g_shift1[D2];
__device__ float g_scale2[D], g_shift2[D];

// ---------------- helpers ----------------------------------------------------
__device__ __forceinline__ uint32_t smem_u32(const void* p) {
    return (uint32_t)__cvta_generic_to_shared(p);
}
__device__ __forceinline__ void ldsm4(uint32_t addr, uint32_t& r0, uint32_t& r1,
                                      uint32_t& r2, uint32_t& r3) {
    asm volatile("ldmatrix.sync.aligned.m8n8.x4.shared.b16 {%0,%1,%2,%3}, [%4];"
                 : "=r"(r0), "=r"(r1), "=r"(r2), "=r"(r3) : "r"(addr));
}
__device__ __forceinline__ void ldsm4t(uint32_t addr, uint32_t& r0, uint32_t& r1,
                                       uint32_t& r2, uint32_t& r3) {
    asm volatile("ldmatrix.sync.aligned.m8n8.x4.trans.shared.b16 {%0,%1,%2,%3}, [%4];"
                 : "=r"(r0), "=r"(r1), "=r"(r2), "=r"(r3) : "r"(addr));
}
__device__ __forceinline__ void mma16816(float* c, const uint32_t* a, const uint32_t* b) {
    asm volatile(
        "mma.sync.aligned.m16n8k16.row.col.f32.bf16.bf16.f32 "
        "{%0,%1,%2,%3}, {%4,%5,%6,%7}, {%8,%9}, {%0,%1,%2,%3};"
        : "+f"(c[0]), "+f"(c[1]), "+f"(c[2]), "+f"(c[3])
        : "r"(a[0]), "r"(a[1]), "r"(a[2]), "r"(a[3]), "r"(b[0]), "r"(b[1]));
}
__device__ __forceinline__ void cp_async16(uint32_t dst, const void* src, int szbytes) {
    asm volatile("cp.async.cg.shared.global [%0], [%1], 16, %2;"
                 :: "r"(dst), "l"(src), "r"(szbytes));
}
__device__ __forceinline__ void cp_commit() { asm volatile("cp.async.commit_group;"); }
__device__ __forceinline__ void cp_wait0() { asm volatile("cp.async.wait_group 0;"); }
__device__ __forceinline__ void split2(float x0, float x1,
                                       __nv_bfloat162& hi, __nv_bfloat162& lo) {
    __nv_bfloat16 h0 = __float2bfloat16_rn(x0);
    __nv_bfloat16 h1 = __float2bfloat16_rn(x1);
    hi = __nv_bfloat162(h0, h1);
    lo = __nv_bfloat162(__float2bfloat16_rn(x0 - __bfloat162float(h0)),
                        __float2bfloat16_rn(x1 - __bfloat162float(h1)));
}

// ---------------- node embedding + z seed + stats zero -----------------------
__global__ void embed_kernel(const int* __restrict__ x,
                             const float* __restrict__ atom_emb,
                             const float* __restrict__ eps_p) {
    int idx = blockIdx.x * blockDim.x + threadIdx.x;
    if (idx < 2 * D2) g_stats1[idx] = 0.f;
    if (idx < 2 * D)  g_stats2[idx] = 0.f;
    int node = idx >> 5, lane = idx & 31;
    if (node >= N_NODES) return;
    const int* xr = x + node * 9;
    float4 acc = make_float4(0.f, 0.f, 0.f, 0.f);
#pragma unroll
    for (int f = 0; f < 9; f++) {
        int v = __ldg(xr + f);
        float4 t = ((const float4*)(atom_emb + (size_t)(f * 64 + v) * D))[lane];
        acc.x += t.x; acc.y += t.y; acc.z += t.z; acc.w += t.w;
    }
    ((float4*)(g_h + (size_t)node * D))[lane] = acc;
    float s = 1.f + __ldg(eps_p);
    acc.x *= s; acc.y *= s; acc.z *= s; acc.w *= s;
    ((float4*)(g_z + (size_t)node * D))[lane] = acc;
}

// ---------------- edge scatter: z[dst] += relu(h[src]+ea)*ew -----------------
__global__ void edge_kernel(const int* __restrict__ edge_index,
                            const int* __restrict__ edge_attr,
                            const float* __restrict__ edge_weight,
                            const float* __restrict__ bond_emb, int l) {
    __shared__ __align__(16) float sb[3 * 8 * D];
    const float* be = bond_emb + (size_t)l * 3 * 8 * D;
    for (int i = threadIdx.x; i < 3 * 8 * D; i += blockDim.x) sb[i] = be[i];
    __syncthreads();

    const int* src = edge_index;
    const int* dst = edge_index + N_EDGES;
    int gw = (blockIdx.x * blockDim.x + threadIdx.x) >> 5;
    int lane = threadIdx.x & 31;
    int nw = (gridDim.x * blockDim.x) >> 5;

    for (int e = gw; e < N_EDGES; e += nw) {
        int s = __ldg(src + e);
        int d = __ldg(dst + e);
        float w = __ldg(edge_weight + e);
        int a0 = __ldg(edge_attr + e * 3 + 0);
        int a1 = __ldg(edge_attr + e * 3 + 1);
        int a2 = __ldg(edge_attr + e * 3 + 2);
        float4 hv = ((const float4*)(g_h + (size_t)s * D))[lane];
        float4 e0 = ((const float4*)(sb + a0 * D))[lane];
        float4 e1 = ((const float4*)(sb + (8 + a1) * D))[lane];
        float4 e2 = ((const float4*)(sb + (16 + a2) * D))[lane];
        float4 m;
        m.x = fmaxf(hv.x + e0.x + e1.x + e2.x, 0.f) * w;
        m.y = fmaxf(hv.y + e0.y + e1.y + e2.y, 0.f) * w;
        m.z = fmaxf(hv.z + e0.z + e1.z + e2.z, 0.f) * w;
        m.w = fmaxf(hv.w + e0.w + e1.w + e2.w, 0.f) * w;
        atomicAdd(((float4*)(g_z + (size_t)d * D)) + lane, m);
    }
}

// ---------------- fp32 -> bf16 hi/lo split (weights preprocess only) ---------
__global__ void split_kernel(const float* __restrict__ src,
                             __nv_bfloat16* __restrict__ dh,
                             __nv_bfloat16* __restrict__ dl, int n4) {
    int i = blockIdx.x * blockDim.x + threadIdx.x;
    if (i >= n4) return;
    float4 v = ((const float4*)src)[i];
    __nv_bfloat162 h0, l0, h1, l1;
    split2(v.x, v.y, h0, l0);
    split2(v.z, v.w, h1, l1);
    ((__nv_bfloat162*)dh)[i * 2]     = h0;
    ((__nv_bfloat162*)dh)[i * 2 + 1] = h1;
    ((__nv_bfloat162*)dl)[i * 2]     = l0;
    ((__nv_bfloat162*)dl)[i * 2 + 1] = l1;
}

// ================ bf16 hi/lo tensor-core GEMM, fused A conversion ============
// C[M x NOUT] = split(act(A_f32)) @ (Bh+Bl) + bias (dropping Al*Bl), + stats.
// act(a) = INBN ? relu(a*insc[k]+insh[k]) : a    (applied before the split)
// 128x128x32 block tile, 256 threads (8 warps: 2M x 4N, 64x32 per warp).
// A path: LDG fp32 (register double-buffer) -> split -> STS bf16 hi/lo.
// B path: cp.async from pre-split weights.
#define A_STRIDE 40    // bf16 per A smem row (80B, conflict-free)
#define B_STRIDE 136   // bf16 per B smem row (272B, conflict-free)
#define GBM 128
#define GBN 128
#define GBK 32
#define A_BYTES (GBM * A_STRIDE * 2)                  // 10240
#define B_BYTES (GBK * B_STRIDE * 2)                  // 8704
#define STAGE_BYTES (2 * A_BYTES + 2 * B_BYTES)       // 37888
#define SMEM_GEMM (2 * STAGE_BYTES)                   // 75776

template <int K, int NOUT, bool INBN>
__global__ __launch_bounds__(256, 2)
void gemm_fused_kernel(const float* __restrict__ A,
                       const __nv_bfloat16* __restrict__ Bh_g,
                       const __nv_bfloat16* __restrict__ Bl_g,
                       const float* __restrict__ bias, float* __restrict__ C,
                       const float* __restrict__ insc, const float* __restrict__ insh,
                       float* __restrict__ stats) {
    const int NT = K / GBK;
    extern __shared__ __align__(16) char smem[];
    __shared__ float ssum[GBN], ssq[GBN];

    int tid = threadIdx.x;
    int lane = tid & 31, warp = tid >> 5;
    int wm = warp & 1, wn = warp >> 1;          // 2 warps M x 4 warps N
    int rowBase = blockIdx.y * GBM;
    int colBase = blockIdx.x * GBN;

    if (tid < GBN) { ssum[tid] = 0.f; ssq[tid] = 0.f; }

    float acc[4][4][4];
#pragma unroll
    for (int i = 0; i < 4; i++)
#pragma unroll
        for (int j = 0; j < 4; j++)
#pragma unroll
            for (int q = 0; q < 4; q++) acc[i][j][q] = 0.f;

    auto pA_h = [&](int s) { return (__nv_bfloat16*)(smem + s * STAGE_BYTES); };
    auto pA_l = [&](int s) { return (__nv_bfloat16*)(smem + s * STAGE_BYTES + A_BYTES); };
    auto pB_h = [&](int s) { return (__nv_bfloat16*)(smem + s * STAGE_BYTES + 2 * A_BYTES); };
    auto pB_l = [&](int s) { return (__nv_bfloat16*)(smem + s * STAGE_BYTES + 2 * A_BYTES + B_BYTES); };

    // A mapping: 128 rows x 32 floats; 2 threads/row, 4 float4 each
    int ar  = tid >> 1;                // 0..127
    int acb = (tid & 1) * 16;          // col base 0 or 16
    int agrow = rowBase + ar;
    bool arow_ok = (agrow < N_NODES);

    float4 areg[4];

    auto LOAD_A = [&](int kt) {
        if (arow_ok) {
            const float* ap = A + (size_t)agrow * K + kt + acb;
            areg[0] = *(const float4*)(ap + 0);
            areg[1] = *(const float4*)(ap + 4);
            areg[2] = *(const float4*)(ap + 8);
            areg[3] = *(const float4*)(ap + 12);
            if (INBN) {
#pragma unroll
                for (int j = 0; j < 4; j++) {
                    float4 sc = *(const float4*)(insc + kt + acb + j * 4);
                    float4 sh = *(const float4*)(insh + kt + acb + j * 4);
                    areg[j].x = fmaxf(fmaf(areg[j].x, sc.x, sh.x), 0.f);
                    areg[j].y = fmaxf(fmaf(areg[j].y, sc.y, sh.y), 0.f);
                    areg[j].z = fmaxf(fmaf(areg[j].z, sc.z, sh.z), 0.f);
                    areg[j].w = fmaxf(fmaf(areg[j].w, sc.w, sh.w), 0.f);
                }
            }
        } else {
            float4 z4 = make_float4(0.f, 0.f, 0.f, 0.f);
            areg[0] = z4; areg[1] = z4; areg[2] = z4; areg[3] = z4;
        }
    };
    auto STORE_A = [&](int s) {
        __nv_bfloat16* dh = pA_h(s) + ar * A_STRIDE + acb;
        __nv_bfloat16* dl = pA_l(s) + ar * A_STRIDE + acb;
#pragma unroll
        for (int j = 0; j < 4; j++) {
            __nv_bfloat162 h0, l0, h1, l1;
            split2(areg[j].x, areg[j].y, h0, l0);
            split2(areg[j].z, areg[j].w, h1, l1);
            *(__nv_bfloat162*)(dh + j * 4)     = h0;
            *(__nv_bfloat162*)(dh + j * 4 + 2) = h1;
            *(__nv_bfloat162*)(dl + j * 4)     = l0;
            *(__nv_bfloat162*)(dl + j * 4 + 2) = l1;
        }
    };
    auto LOAD_B = [&](int kt, int s) {
#pragma unroll
        for (int i = 0; i < 2; i++) {
            int id = tid + i * 256;
            int r = id >> 4, c = (id & 15) * 8;
            cp_async16(smem_u32(pB_h(s) + r * B_STRIDE + c),
                       Bh_g + (size_t)(kt + r) * NOUT + colBase + c, 16);
            cp_async16(smem_u32(pB_l(s) + r * B_STRIDE + c),
                       Bl_g + (size_t)(kt + r) * NOUT + colBase + c, 16);
        }
    };

    int lr = lane & 15;
    int lc = (lane >> 4) << 3;

    // prologue: tile 0
    LOAD_B(0, 0); cp_commit();
    LOAD_A(0);
    STORE_A(0);
    cp_wait0();
    __syncthreads();

    int buf = 0;
#pragma unroll 1
    for (int t = 0; t < NT; t++) {
        if (t + 1 < NT) {
            LOAD_B((t + 1) * GBK, buf ^ 1);
            cp_commit();
            LOAD_A((t + 1) * GBK);     // LDG in flight during compute below
        }

        const __nv_bfloat16* Ahs = pA_h(buf);
        const __nv_bfloat16* Als = pA_l(buf);
        const __nv_bfloat16* Bhs = pB_h(buf);
        const __nv_bfloat16* Bls = pB_l(buf);
#pragma unroll
        for (int ks = 0; ks < GBK; ks += 16) {
            uint32_t bh[4][2], bl[4][2];
#pragma unroll
            for (int nb = 0; nb < 2; nb++) {
                int ncol = wn * 32 + nb * 16 + lc;
                uint32_t r0, r1, r2, r3;
                ldsm4t(smem_u32(Bhs + (ks + lr) * B_STRIDE + ncol), r0, r1, r2, r3);
                bh[nb * 2][0] = r0; bh[nb * 2][1] = r1;
                bh[nb * 2 + 1][0] = r2; bh[nb * 2 + 1][1] = r3;
                ldsm4t(smem_u32(Bls + (ks + lr) * B_STRIDE + ncol), r0, r1, r2, r3);
                bl[nb * 2][0] = r0; bl[nb * 2][1] = r1;
                bl[nb * 2 + 1][0] = r2; bl[nb * 2 + 1][1] = r3;
            }
#pragma unroll
            for (int mf = 0; mf < 4; mf++) {
                int mrow = wm * 64 + mf * 16 + lr;
                uint32_t ah[4], al[4];
                ldsm4(smem_u32(Ahs + mrow * A_STRIDE + ks + lc), ah[0], ah[1], ah[2], ah[3]);
                ldsm4(smem_u32(Als + mrow * A_STRIDE + ks + lc), al[0], al[1], al[2], al[3]);
#pragma unroll
                for (int nf = 0; nf < 4; nf++) {
                    mma16816(acc[mf][nf], ah, bh[nf]);
                    mma16816(acc[mf][nf], ah, bl[nf]);
                    mma16816(acc[mf][nf], al, bh[nf]);
                }
            }
        }

        if (t + 1 < NT) {
            STORE_A(buf ^ 1);          // safe: stage buf^1 last read at tile t-1
            cp_wait0();
            __syncthreads();
            buf ^= 1;
        }
    }

    // ---- epilogue: bias, store, per-column stats ----
    int crow = lane >> 2;
    int ccol = (lane & 3) * 2;
    float bcol8[4][2];
#pragma unroll
    for (int nf = 0; nf < 4; nf++) {
        bcol8[nf][0] = bias[colBase + wn * 32 + nf * 8 + ccol];
        bcol8[nf][1] = bias[colBase + wn * 32 + nf * 8 + ccol + 1];
    }
    float psum[4][2] = {}, psq[4][2] = {};
#pragma unroll
    for (int mf = 0; mf < 4; mf++)
#pragma unroll
        for (int r2 = 0; r2 < 2; r2++) {
            int r = rowBase + wm * 64 + mf * 16 + crow + r2 * 8;
            if (r < N_NODES) {
#pragma unroll
                for (int nf = 0; nf < 4; nf++) {
                    float v0 = acc[mf][nf][r2 * 2 + 0] + bcol8[nf][0];
                    float v1 = acc[mf][nf][r2 * 2 + 1] + bcol8[nf][1];
                    *(float2*)(C + (size_t)r * NOUT + colBase + wn * 32 + nf * 8 + ccol) =
                        make_float2(v0, v1);
                    psum[nf][0] += v0; psq[nf][0] += v0 * v0;
                    psum[nf][1] += v1; psq[nf][1] += v1 * v1;
                }
            }
        }
    __syncthreads();
#pragma unroll
    for (int nf = 0; nf < 4; nf++) {
        int c = wn * 32 + nf * 8 + ccol;
        atomicAdd(&ssum[c],     psum[nf][0]);
        atomicAdd(&ssum[c + 1], psum[nf][1]);
        atomicAdd(&ssq[c],      psq[nf][0]);
        atomicAdd(&ssq[c + 1],  psq[nf][1]);
    }
    __syncthreads();
    if (tid < GBN) {
        atomicAdd(&stats[colBase + tid], ssum[tid]);
        atomicAdd(&stats[NOUT + colBase + tid], ssq[tid]);
    }
}

// ---------------- BN stats -> scale/shift (and re-zero stats) ----------------
__global__ void finalize_kernel(float* __restrict__ stats,
                                const float* __restrict__ g, const float* __restrict__ b,
                                float* __restrict__ scale, float* __restrict__ shift, int C) {
    int c = threadIdx.x;
    if (c < C) {
        const float invn = 1.f / (float)N_NODES;
        float m = stats[c] * invn;
        float var = stats[C + c] * invn - m * m;
        float sc = g[c] * rsqrtf(var + 1e-5f);
        scale[c] = sc;
        shift[c] = b[c] - m * sc;
        stats[c] = 0.f;
        stats[C + c] = 0.f;
    }
}

// ---------------- apply BN2; write h + next-layer z seed (or final out) ------
__global__ void bn_apply_kernel(float* __restrict__ final_out,
                                const float* __restrict__ eps_p, int l) {
    int idx = blockIdx.x * blockDim.x + threadIdx.x;
    if (idx >= N_NODES * (D / 4)) return;
    int c4 = idx & 31;
    float4 v = ((const float4*)g_z)[idx];
    float4 sc = ((const float4*)g_scale2)[c4];
    float4 sh = ((const float4*)g_shift2)[c4];
    v.x = fmaf(v.x, sc.x, sh.x);
    v.y = fmaf(v.y, sc.y, sh.y);
    v.z = fmaf(v.z, sc.z, sh.z);
    v.w = fmaf(v.w, sc.w, sh.w);
    if (l < NLAYERS - 1) {
        v.x = fmaxf(v.x, 0.f); v.y = fmaxf(v.y, 0.f);
        v.z = fmaxf(v.z, 0.f); v.w = fmaxf(v.w, 0.f);
        ((float4*)g_h)[idx] = v;
        float s = 1.f + __ldg(eps_p + l + 1);
        v.x *= s; v.y *= s; v.z *= s; v.w *= s;
        ((float4*)g_z)[idx] = v;
    } else {
        ((float4*)final_out)[idx] = v;
    }
}

// ---------------- launcher ---------------------------------------------------
extern "C" void kernel_launch(void* const* d_in, const int* in_sizes, int n_in,
                              void* d_out, int out_size) {
    const int*   x           = (const int*)d_in[0];
    const int*   edge_index  = (const int*)d_in[1];
    const int*   edge_attr   = (const int*)d_in[2];
    const float* edge_weight = (const float*)d_in[3];
    const float* atom_emb    = (const float*)d_in[4];
    const float* bond_emb    = (const float*)d_in[5];
    const float* W1          = (const float*)d_in[6];
    const float* b1          = (const float*)d_in[7];
    const float* bn1_g       = (const float*)d_in[8];
    const float* bn1_b       = (const float*)d_in[9];
    const float* W2          = (const float*)d_in[10];
    const float* b2          = (const float*)d_in[11];
    const float* eps_p       = (const float*)d_in[12];
    const float* bn_g        = (const float*)d_in[13];
    const float* bn_b        = (const float*)d_in[14];
    float* out = (float*)d_out;

    float *p_z, *p_y1, *p_sc1, *p_sh1, *p_st1, *p_st2, *p_sc2, *p_sh2;
    __nv_bfloat16 *p_w1h, *p_w1l, *p_w2h, *p_w2l;
    cudaGetSymbolAddress((void**)&p_z,   g_z);
    cudaGetSymbolAddress((void**)&p_y1,  g_y1);
    cudaGetSymbolAddress((void**)&p_sc1, g_scale1);
    cudaGetSymbolAddress((void**)&p_sh1, g_shift1);
    cudaGetSymbolAddress((void**)&p_st1, g_stats1);
    cudaGetSymbolAddress((void**)&p_st2, g_stats2);
    cudaGetSymbolAddress((void**)&p_sc2, g_scale2);
    cudaGetSymbolAddress((void**)&p_sh2, g_shift2);
    cudaGetSymbolAddress((void**)&p_w1h, g_w1h);
    cudaGetSymbolAddress((void**)&p_w1l, g_w1l);
    cudaGetSymbolAddress((void**)&p_w2h, g_w2h);
    cudaGetSymbolAddress((void**)&p_w2l, g_w2l);

    cudaFuncSetAttribute(gemm_fused_kernel<D, D2, false>,
                         cudaFuncAttributeMaxDynamicSharedMemorySize, SMEM_GEMM);
    cudaFuncSetAttribute(gemm_fused_kernel<D2, D, true>,
                         cudaFuncAttributeMaxDynamicSharedMemorySize, SMEM_GEMM);

    const int ELT_BLOCKS = (N_NODES * (D / 4) + 255) / 256;
    const int MB = (N_NODES + GBM - 1) / GBM;
    const int WN4 = NLAYERS * D * D2 / 4;

    embed_kernel<<<(N_NODES * 32 + 255) / 256, 256>>>(x, atom_emb, eps_p);
    split_kernel<<<(WN4 + 255) / 256, 256>>>(W1, p_w1h, p_w1l, WN4);
    split_kernel<<<(WN4 + 255) / 256, 256>>>(W2, p_w2h, p_w2l, WN4);

    for (int l = 0; l < NLAYERS; l++) {
        edge_kernel<<<1184, 256>>>(edge_index, edge_attr, edge_weight, bond_emb, l);

        gemm_fused_kernel<D, D2, false><<<dim3(D2 / GBN, MB), 256, SMEM_GEMM>>>(
            p_z, p_w1h + (size_t)l * D * D2, p_w1l + (size_t)l * D * D2,
            b1 + (size_t)l * D2, p_y1, nullptr, nullptr, p_st1);
        finalize_kernel<<<1, 256>>>(p_st1, bn1_g + (size_t)l * D2, bn1_b + (size_t)l * D2,
                                    p_sc1, p_sh1, D2);

        gemm_fused_kernel<D2, D, true><<<dim3(D / GBN, MB), 256, SMEM_GEMM>>>(
            p_y1, p_w2h + (size_t)l * D2 * D, p_w2l + (size_t)l * D2 * D,
            b2 + (size_t)l * D, p_z, p_sc1, p_sh1, p_st2);
        finalize_kernel<<<1, 128>>>(p_st2, bn_g + (size_t)l * D, bn_b + (size_t)l * D,
                                    p_sc2, p_sh2, D);

        bn_apply_kernel<<<ELT_BLOCKS, 256>>>(out, eps_p, l);
    }
    (void)in_sizes; (void)n_in; (void)out_size;
}